// round 12
// baseline (speedup 1.0000x reference)
#include <cuda_runtime.h>
#include <cuda_bf16.h>
#include <math.h>
#include <stdint.h>

// ---------------- problem constants ----------------
#define NT      26
#define TROWS   100001
#define EDIM    64
#define BATCH   8192
#define LOOKUPS 4
#define NF      27
#define NPAIR   351
#define RDIM    415
#define RKP     448
#define FSTR    68

// ---------------- scratch (allocation-free device globals) ----------------
// bf16 [hi|lo] pair buffers, row stride 2*Kp.
__device__ __align__(16) __nv_bfloat16 g_h0[(size_t)BATCH * 1024];  // Kp=512
__device__ __align__(16) __nv_bfloat16 g_a1[(size_t)BATCH * 512];   // Kp=256
__device__ __align__(16) __nv_bfloat16 g_Rp[(size_t)BATCH * 896];   // Kp=448
__device__ __align__(16) __nv_bfloat16 g_t0[(size_t)BATCH * 1024];  // Kp=512
__device__ __align__(16) float g_xbot[(size_t)BATCH * EDIM];
__device__ __align__(16) float g_t1[(size_t)BATCH * 256];
// weight [hi|lo] pairs
__device__ __align__(16) __nv_bfloat16 g_wb1[256 * 1024];
__device__ __align__(16) __nv_bfloat16 g_wb2[64  * 512];
__device__ __align__(16) __nv_bfloat16 g_wt0[512 * 896];
__device__ __align__(16) __nv_bfloat16 g_wt1[256 * 1024];
__device__ int g_idx64;

// ---------------- helpers ----------------
__device__ __forceinline__ uint32_t smem_u32(const void* p) {
    uint32_t a;
    asm("{ .reg .u64 t; cvta.to.shared.u64 t, %1; cvt.u32.u64 %0, t; }" : "=r"(a) : "l"(p));
    return a;
}
__device__ __forceinline__ uint32_t sw128(uint32_t o) { return o ^ ((o >> 3) & 0x70); }

#define CP_ASYNC16(dst, src) \
    asm volatile("cp.async.cg.shared.global [%0], [%1], 16;" :: "r"(dst), "l"(src))
#define CP_COMMIT() asm volatile("cp.async.commit_group;" ::: "memory")
#define CP_WAIT(n)  asm volatile("cp.async.wait_group %0;" :: "n"(n) : "memory")

#define LDSM_X4(r0, r1, r2, r3, a) \
    asm volatile("ldmatrix.sync.aligned.m8n8.x4.shared.b16 {%0,%1,%2,%3}, [%4];" \
                 : "=r"(r0), "=r"(r1), "=r"(r2), "=r"(r3) : "r"(a))

#define MMA16816(c, a0, a1, a2, a3, b0, b1) \
    asm volatile("mma.sync.aligned.m16n8k16.row.col.f32.bf16.bf16.f32 " \
                 "{%0,%1,%2,%3},{%4,%5,%6,%7},{%8,%9},{%0,%1,%2,%3};" \
                 : "+f"((c)[0]), "+f"((c)[1]), "+f"((c)[2]), "+f"((c)[3]) \
                 : "r"(a0), "r"(a1), "r"(a2), "r"(a3), "r"(b0), "r"(b1))

__device__ __forceinline__ void write2(__nv_bfloat16* row, int Kp, int j, float v) {
    __nv_bfloat16 hi = __float2bfloat16(v);
    __nv_bfloat16 lo = __float2bfloat16(v - __bfloat162float(hi));
    row[j] = hi; row[Kp + j] = lo;
}
__device__ __forceinline__ void store_pair2(__nv_bfloat16* base, int Kp,
                                            float v0, float v1) {
    __nv_bfloat16 h0 = __float2bfloat16(v0);
    __nv_bfloat16 h1 = __float2bfloat16(v1);
    __nv_bfloat16 l0 = __float2bfloat16(v0 - __bfloat162float(h0));
    __nv_bfloat16 l1 = __float2bfloat16(v1 - __bfloat162float(h1));
    *(__nv_bfloat162*)(base)      = __nv_bfloat162(h0, h1);
    *(__nv_bfloat162*)(base + Kp) = __nv_bfloat162(l0, l1);
}

// ---------------- index dtype probe ----------------
__global__ void detect_kernel(const int* __restrict__ lsi_raw) {
    if (threadIdx.x == 0 && blockIdx.x == 0) {
        int ok = 1;
        for (int p = 0; p < 32; p++) {
            int lo = lsi_raw[2 * p], hi = lsi_raw[2 * p + 1];
            if (hi != 0 || (unsigned)lo > 100000u) { ok = 0; break; }
        }
        g_idx64 = ok;
    }
}

// ---------------- merged weight convert -----------------------------------
#define WC0 (256 * 512)
#define WC1 (64 * 256)
#define WC2 (512 * 448)
#define WC3 (256 * 512)
#define WCTOT (WC0 + WC1 + WC2 + WC3)
__global__ void wconv_all(const float* __restrict__ w1, const float* __restrict__ w2,
                          const float* __restrict__ w3, const float* __restrict__ w4)
{
    int i = blockIdx.x * 256 + threadIdx.x;
    if (i >= WCTOT) return;
    if (i < WC0) {
        int n = i >> 9, k = i & 511;
        write2(g_wb1 + (size_t)n * 1024, 512, k, w1[n * 512 + k]);
    } else if (i < WC0 + WC1) {
        i -= WC0;
        int n = i >> 8, k = i & 255;
        write2(g_wb2 + (size_t)n * 512, 256, k, w2[n * 256 + k]);
    } else if (i < WC0 + WC1 + WC2) {
        i -= WC0 + WC1;
        int n = i / 448, k = i % 448;
        float v = (k < RDIM) ? w3[n * RDIM + k] : 0.0f;
        write2(g_wt0 + (size_t)n * 896, 448, k, v);
    } else {
        i -= WC0 + WC1 + WC2;
        int n = i >> 9, k = i & 511;
        write2(g_wt1 + (size_t)n * 1024, 512, k, w4[n * 512 + k]);
    }
}

// ---------------- bottom layer0: 13 -> 512, pair out -----------------------
#define B0_ROWS 32
__global__ void __launch_bounds__(256) bot0_kernel(
    const float* __restrict__ x,
    const float* __restrict__ w, const float* __restrict__ b)
{
    __shared__ float ws[512 * 13];
    __shared__ float bs[512];
    __shared__ float xs[B0_ROWS * 13];
    const int tid  = threadIdx.x;
    const int row0 = blockIdx.x * B0_ROWS;

    for (int i = tid; i < 512 * 13; i += 256) ws[i] = w[i];
    for (int i = tid; i < 512; i += 256)      bs[i] = b[i];
    for (int i = tid; i < B0_ROWS * 13; i += 256) xs[i] = x[row0 * 13 + i];
    __syncthreads();

    for (int o = tid; o < B0_ROWS * 512; o += 256) {
        int r = o >> 9, j = o & 511;
        float acc = bs[j];
        const float* xr = xs + r * 13;
        const float* wr = ws + j * 13;
#pragma unroll
        for (int k = 0; k < 13; k++) acc += xr[k] * wr[k];
        write2(g_h0 + (size_t)(row0 + r) * 1024, 512, j, fmaxf(acc, 0.0f));
    }
}

// ---------------- mma.sync bf16 GEMM, 3-stage cp.async ---------------------
// A2/W2: [hi|lo] pairs, stride 2*Kp; logical [hi|lo|hi]x[hi|hi|lo] via chunk
// remap. BM in {128,64}, BN=64, BK=64. 256 threads: 4(M)x2(N) warps.
// BM=64 -> 4 CTAs/SM; BM=128 -> 3 CTAs/SM.
// mode 0: fp32 out Cf[ldc]; mode 1: [hi|lo] pair out C2 (Kp=KpOut).
#define NSTAGE 3
template<int BM>
__global__ void __launch_bounds__(256, (BM == 128 ? 3 : 4)) gemm_mma(
    const __nv_bfloat16* __restrict__ A2,
    const __nv_bfloat16* __restrict__ W2,
    const float* __restrict__ bias, int Kp,
    float* __restrict__ Cf, int ldc,
    __nv_bfloat16* __restrict__ C2, int KpOut, int mode)
{
    constexpr int MT     = BM / 64;          // m16 frags per warp
    constexpr int NBA    = BM / 32;          // A cp.async per thread
    constexpr int ABYTES = BM * 128;
    constexpr int STAGEB = ABYTES + 64 * 128;

    extern __shared__ char dynsm[];
    const int tid  = threadIdx.x;
    const int wid  = tid >> 5;
    const int lane = tid & 31;
    const int warp_m = wid & 3;
    const int warp_n = wid >> 2;
    const size_t row0 = (size_t)blockIdx.x * BM;
    const size_t col0 = (size_t)blockIdx.y * 64;

    uint32_t dbase = smem_u32(dynsm);
    uint32_t abase = (dbase + 1023) & ~1023u;

    const int lrow = tid >> 3;
    const int lcol = tid & 7;
    const int K2 = 2 * Kp;
    const int nz  = Kp / 64;
    const int nch = 3 * nz;
    const __nv_bfloat16* Abase = A2 + (row0 + lrow) * (size_t)K2 + lcol * 8;
    const __nv_bfloat16* Wbase = W2 + (col0 + lrow) * (size_t)K2 + lcol * 8;
    const uint32_t adst = sw128(lrow * 128 + lcol * 16);   // row-q adds 32*128

    // issue chunk t's loads into stage s
    auto issue = [&](int t, int s) {
        const int at = (t < 2 * nz) ? t : t - 2 * nz;      // A: [hi|lo|hi]
        const int wt = (t < nz)     ? t : t - nz;          // W: [hi|hi|lo]
        const uint32_t sb = abase + s * STAGEB;
        const __nv_bfloat16* Ab = Abase + at * 64;
        const __nv_bfloat16* Wb = Wbase + wt * 64;
#pragma unroll
        for (int q = 0; q < NBA; q++)
            CP_ASYNC16(sb + adst + q * 32 * 128, Ab + (size_t)q * 32 * K2);
#pragma unroll
        for (int q = 0; q < 2; q++)
            CP_ASYNC16(sb + ABYTES + adst + q * 32 * 128, Wb + (size_t)q * 32 * K2);
    };

    // ldmatrix lane offsets (relative to stage base)
    int abyte[MT], bbyte[2];
#pragma unroll
    for (int tm = 0; tm < MT; tm++)
        abyte[tm] = (warp_m * MT * 16 + tm * 16 + (lane & 15)) * 128 + (lane >> 4) * 16;
#pragma unroll
    for (int g = 0; g < 2; g++)
        bbyte[g] = (warp_n * 32 + g * 16 + (lane & 15)) * 128 + (lane >> 4) * 16;

    // accumulators (+bias)
    float c[MT][4][4];
    {
        const int cb = (int)col0 + warp_n * 32 + 2 * (lane & 3);
#pragma unroll
        for (int tn = 0; tn < 4; tn++) {
            float b0v = bias[cb + tn * 8];
            float b1v = bias[cb + tn * 8 + 1];
#pragma unroll
            for (int tm = 0; tm < MT; tm++) {
                c[tm][tn][0] = b0v; c[tm][tn][1] = b1v;
                c[tm][tn][2] = b0v; c[tm][tn][3] = b1v;
            }
        }
    }

    // prologue: stages 0,1 in flight
    issue(0, 0); CP_COMMIT();
    issue(1, 1); CP_COMMIT();

    for (int t = 0; t < nch; t++) {
        __syncthreads();                       // all warps done with stage (t+2)%3
        if (t + 2 < nch) { issue(t + 2, (t + 2) % NSTAGE); CP_COMMIT(); }
        const int rem = nch - 1 - t;
        if (rem >= 2)      CP_WAIT(2);
        else if (rem == 1) CP_WAIT(1);
        else               CP_WAIT(0);
        __syncthreads();                       // stage t visible to all warps

        const uint32_t sbase = abase + (t % NSTAGE) * STAGEB;
        const uint32_t bbase = sbase + ABYTES;
#pragma unroll
        for (int s = 0; s < 4; s++) {
            uint32_t af[MT][4];
#pragma unroll
            for (int tm = 0; tm < MT; tm++)
                LDSM_X4(af[tm][0], af[tm][1], af[tm][2], af[tm][3],
                        sbase + sw128(abyte[tm] + s * 32));
            // serialize B groups: lower register pressure
#pragma unroll
            for (int g = 0; g < 2; g++) {
                uint32_t b0, b1, b2, b3;
                LDSM_X4(b0, b1, b2, b3, bbase + sw128(bbyte[g] + s * 32));
#pragma unroll
                for (int tm = 0; tm < MT; tm++) {
                    MMA16816(c[tm][g * 2 + 0],
                             af[tm][0], af[tm][1], af[tm][2], af[tm][3], b0, b2);
                    MMA16816(c[tm][g * 2 + 1],
                             af[tm][0], af[tm][1], af[tm][2], af[tm][3], b1, b3);
                }
            }
        }
    }

    // epilogue: fragments straight to global
#pragma unroll
    for (int tm = 0; tm < MT; tm++) {
        const size_t r = row0 + warp_m * MT * 16 + tm * 16 + (lane >> 2);
#pragma unroll
        for (int tn = 0; tn < 4; tn++) {
            const size_t cc = col0 + warp_n * 32 + tn * 8 + 2 * (lane & 3);
            float v0 = fmaxf(c[tm][tn][0], 0.0f);
            float v1 = fmaxf(c[tm][tn][1], 0.0f);
            float v2 = fmaxf(c[tm][tn][2], 0.0f);
            float v3 = fmaxf(c[tm][tn][3], 0.0f);
            if (mode == 0) {
                *(float2*)(Cf + r * ldc + cc)       = make_float2(v0, v1);
                *(float2*)(Cf + (r + 8) * ldc + cc) = make_float2(v2, v3);
            } else {
                store_pair2(C2 + r * (size_t)(2 * KpOut) + cc,       KpOut, v0, v1);
                store_pair2(C2 + (r + 8) * (size_t)(2 * KpOut) + cc, KpOut, v2, v3);
            }
        }
    }
}

// ---------------- embedding gather + interaction -> R pair -----------------
__global__ void __launch_bounds__(256) embed_kernel(
    const void*  __restrict__ lsi_raw,
    const float* __restrict__ emb)
{
    __shared__ __align__(16) float F[NF * FSTR];
    __shared__ int sidx[NT * LOOKUPS];

    const int b    = blockIdx.x;
    const int tid  = threadIdx.x;
    const int is64 = g_idx64;

    if (tid < NT * LOOKUPS) {
        int t = tid >> 2, l = tid & 3;
        long long off = (long long)t * (BATCH * LOOKUPS) + (long long)b * LOOKUPS + l;
        int idx = is64 ? (int)((const long long*)lsi_raw)[off]
                       : ((const int*)lsi_raw)[off];
        sidx[tid] = idx;
    }
    if (tid < EDIM)
        F[tid] = g_xbot[(size_t)b * EDIM + tid];
    __syncthreads();

    for (int q = tid; q < NT * 16; q += 256) {
        int t = q >> 4, v = q & 15;
        const float4* base = (const float4*)(emb + (size_t)t * TROWS * EDIM) + v;
        float4 acc = make_float4(0.f, 0.f, 0.f, 0.f);
#pragma unroll
        for (int l = 0; l < LOOKUPS; l++) {
            float4 e = base[(size_t)sidx[t * 4 + l] * 16];
            acc.x += e.x; acc.y += e.y; acc.z += e.z; acc.w += e.w;
        }
        acc.x *= 0.25f; acc.y *= 0.25f; acc.z *= 0.25f; acc.w *= 0.25f;
        *(float4*)(F + (t + 1) * FSTR + v * 4) = acc;
    }
    __syncthreads();

    __nv_bfloat16* Rrow = g_Rp + (size_t)b * 896;
    if (tid < EDIM) write2(Rrow, RKP, tid, F[tid]);
    for (int j = RDIM + tid; j < RKP; j += 256) write2(Rrow, RKP, j, 0.0f);

    for (int p = tid; p < NPAIR; p += 256) {
        int i = (int)((1.0f + sqrtf(1.0f + 8.0f * (float)p)) * 0.5f);
        while (i * (i - 1) / 2 > p) i--;
        while ((i + 1) * i / 2 <= p) i++;
        int j = p - i * (i - 1) / 2;
        const float* Fi = F + i * FSTR;
        const float* Fj = F + j * FSTR;
        float acc = 0.0f;
#pragma unroll 16
        for (int k = 0; k < EDIM; k++) acc += Fi[k] * Fj[k];
        write2(Rrow, RKP, 64 + p, acc);
    }
}

// ---------------- top layer2: 256 -> 1 (warp per row) ----------------------
__global__ void __launch_bounds__(256) top2_kernel(
    const float* __restrict__ A,
    const float* __restrict__ w, const float* __restrict__ b,
    float* __restrict__ out)
{
    const int warp = threadIdx.x >> 5, lane = threadIdx.x & 31;
    const int row  = blockIdx.x * 8 + warp;
    const float* a = A + (size_t)row * 256;
    float4 a0 = *(const float4*)(a + lane * 4);
    float4 a1 = *(const float4*)(a + 128 + lane * 4);
    float4 w0 = *(const float4*)(w + lane * 4);
    float4 w1 = *(const float4*)(w + 128 + lane * 4);
    float acc = a0.x * w0.x + a0.y * w0.y + a0.z * w0.z + a0.w * w0.w
              + a1.x * w1.x + a1.y * w1.y + a1.z * w1.z + a1.w * w1.w;
#pragma unroll
    for (int o = 16; o; o >>= 1) acc += __shfl_down_sync(0xffffffffu, acc, o);
    if (lane == 0) out[row] = acc + b[0];
}

// ---------------- launch ----------------
extern "C" void kernel_launch(void* const* d_in, const int* in_sizes, int n_in,
                              void* d_out, int out_size)
{
    const float* dense_x = (const float*)d_in[0];
    const void*  lsi     = d_in[2];
    const float* emb     = (const float*)d_in[3];
    const float* bw0 = (const float*)d_in[4];
    const float* bb0 = (const float*)d_in[5];
    const float* bw1 = (const float*)d_in[6];
    const float* bb1 = (const float*)d_in[7];
    const float* bw2 = (const float*)d_in[8];
    const float* bb2 = (const float*)d_in[9];
    const float* tw0 = (const float*)d_in[10];
    const float* tb0 = (const float*)d_in[11];
    const float* tw1 = (const float*)d_in[12];
    const float* tb1 = (const float*)d_in[13];
    const float* tw2 = (const float*)d_in[14];
    const float* tb2 = (const float*)d_in[15];
    float* out = (float*)d_out;

    __nv_bfloat16 *h0, *a1, *Rp, *t0, *wb1, *wb2, *wt0, *wt1;
    float *xbot, *t1;
    cudaGetSymbolAddress((void**)&h0,  g_h0);
    cudaGetSymbolAddress((void**)&a1,  g_a1);
    cudaGetSymbolAddress((void**)&Rp,  g_Rp);
    cudaGetSymbolAddress((void**)&t0,  g_t0);
    cudaGetSymbolAddress((void**)&wb1, g_wb1);
    cudaGetSymbolAddress((void**)&wb2, g_wb2);
    cudaGetSymbolAddress((void**)&wt0, g_wt0);
    cudaGetSymbolAddress((void**)&wt1, g_wt1);
    cudaGetSymbolAddress((void**)&xbot, g_xbot);
    cudaGetSymbolAddress((void**)&t1,   g_t1);

    const int dyn64 = 1024 + NSTAGE * (64 * 128 + 64 * 128);   // 50176
    cudaFuncSetAttribute(gemm_mma<64>, cudaFuncAttributeMaxDynamicSharedMemorySize, dyn64);

    detect_kernel<<<1, 32>>>((const int*)lsi);
    wconv_all<<<(WCTOT + 255) / 256, 256>>>(bw1, bw2, tw0, tw1);

    // bottom MLP
    bot0_kernel<<<BATCH / B0_ROWS, 256>>>(dense_x, bw0, bb0);
    gemm_mma<64><<<dim3(BATCH / 64, 4), 256, dyn64>>>(h0, wb1, bb1, 512,
                                                      nullptr, 0, a1, 256, 1);
    gemm_mma<64><<<dim3(BATCH / 64, 1), 256, dyn64>>>(a1, wb2, bb2, 256,
                                                      xbot, 64, nullptr, 0, 0);
    // embeddings + interaction -> R pair
    embed_kernel<<<BATCH, 256>>>(lsi, emb);

    // top MLP
    gemm_mma<64><<<dim3(BATCH / 64, 8), 256, dyn64>>>(Rp, wt0, tb0, 448,
                                                      nullptr, 0, t0, 512, 1);
    gemm_mma<64><<<dim3(BATCH / 64, 4), 256, dyn64>>>(t0, wt1, tb1, 512,
                                                      t1, 256, nullptr, 0, 0);
    top2_kernel<<<BATCH / 8, 256>>>(t1, tw2, tb2, out);
}

// round 15
// speedup vs baseline: 1.0948x; 1.0948x over previous
#include <cuda_runtime.h>
#include <cuda_bf16.h>
#include <math.h>
#include <stdint.h>

// ---------------- problem constants ----------------
#define NT      26
#define TROWS   100001
#define EDIM    64
#define BATCH   8192
#define LOOKUPS 4
#define NF      27
#define NPAIR   351
#define RDIM    415
#define RKP     448
#define FSTR    68

// ---------------- scratch (allocation-free device globals) ----------------
// bf16 [hi|lo] pair buffers, row stride 2*Kp.
__device__ __align__(16) __nv_bfloat16 g_h0[(size_t)BATCH * 1024];  // Kp=512
__device__ __align__(16) __nv_bfloat16 g_a1[(size_t)BATCH * 512];   // Kp=256
__device__ __align__(16) __nv_bfloat16 g_Rp[(size_t)BATCH * 896];   // Kp=448
__device__ __align__(16) __nv_bfloat16 g_t0[(size_t)BATCH * 1024];  // Kp=512
__device__ __align__(16) float g_xbot[(size_t)BATCH * EDIM];
__device__ __align__(16) float g_t1[(size_t)BATCH * 256];
// weight [hi|lo] pairs
__device__ __align__(16) __nv_bfloat16 g_wb1[256 * 1024];
__device__ __align__(16) __nv_bfloat16 g_wb2[64  * 512];
__device__ __align__(16) __nv_bfloat16 g_wt0[512 * 896];
__device__ __align__(16) __nv_bfloat16 g_wt1[256 * 1024];
__device__ int g_idx64;

// ---------------- helpers ----------------
__device__ __forceinline__ uint32_t smem_u32(const void* p) {
    uint32_t a;
    asm("{ .reg .u64 t; cvta.to.shared.u64 t, %1; cvt.u32.u64 %0, t; }" : "=r"(a) : "l"(p));
    return a;
}
__device__ __forceinline__ uint32_t sw128(uint32_t o) { return o ^ ((o >> 3) & 0x70); }

#define CP_ASYNC16(dst, src) \
    asm volatile("cp.async.cg.shared.global [%0], [%1], 16;" :: "r"(dst), "l"(src))
#define CP_COMMIT() asm volatile("cp.async.commit_group;" ::: "memory")
#define CP_WAIT(n)  asm volatile("cp.async.wait_group %0;" :: "n"(n) : "memory")

#define LDSM_X4(r0, r1, r2, r3, a) \
    asm volatile("ldmatrix.sync.aligned.m8n8.x4.shared.b16 {%0,%1,%2,%3}, [%4];" \
                 : "=r"(r0), "=r"(r1), "=r"(r2), "=r"(r3) : "r"(a))

#define MMA16816(c, a0, a1, a2, a3, b0, b1) \
    asm volatile("mma.sync.aligned.m16n8k16.row.col.f32.bf16.bf16.f32 " \
                 "{%0,%1,%2,%3},{%4,%5,%6,%7},{%8,%9},{%0,%1,%2,%3};" \
                 : "+f"((c)[0]), "+f"((c)[1]), "+f"((c)[2]), "+f"((c)[3]) \
                 : "r"(a0), "r"(a1), "r"(a2), "r"(a3), "r"(b0), "r"(b1))

__device__ __forceinline__ void write2(__nv_bfloat16* row, int Kp, int j, float v) {
    __nv_bfloat16 hi = __float2bfloat16(v);
    __nv_bfloat16 lo = __float2bfloat16(v - __bfloat162float(hi));
    row[j] = hi; row[Kp + j] = lo;
}
__device__ __forceinline__ void store_pair2(__nv_bfloat16* base, int Kp,
                                            float v0, float v1) {
    __nv_bfloat16 h0 = __float2bfloat16(v0);
    __nv_bfloat16 h1 = __float2bfloat16(v1);
    __nv_bfloat16 l0 = __float2bfloat16(v0 - __bfloat162float(h0));
    __nv_bfloat16 l1 = __float2bfloat16(v1 - __bfloat162float(h1));
    *(__nv_bfloat162*)(base)      = __nv_bfloat162(h0, h1);
    *(__nv_bfloat162*)(base + Kp) = __nv_bfloat162(l0, l1);
}
// split into smem-staged hi/lo (bf16) halves
__device__ __forceinline__ void split2s(__nv_bfloat16* sm, int j, float v) {
    __nv_bfloat16 hi = __float2bfloat16(v);
    __nv_bfloat16 lo = __float2bfloat16(v - __bfloat162float(hi));
    sm[j] = hi; sm[RKP + j] = lo;
}

// ---------------- index dtype probe ----------------
__global__ void detect_kernel(const int* __restrict__ lsi_raw) {
    if (threadIdx.x == 0 && blockIdx.x == 0) {
        int ok = 1;
        for (int p = 0; p < 32; p++) {
            int lo = lsi_raw[2 * p], hi = lsi_raw[2 * p + 1];
            if (hi != 0 || (unsigned)lo > 100000u) { ok = 0; break; }
        }
        g_idx64 = ok;
    }
}

// ---------------- merged weight convert -----------------------------------
#define WC0 (256 * 512)
#define WC1 (64 * 256)
#define WC2 (512 * 448)
#define WC3 (256 * 512)
#define WCTOT (WC0 + WC1 + WC2 + WC3)
__global__ void wconv_all(const float* __restrict__ w1, const float* __restrict__ w2,
                          const float* __restrict__ w3, const float* __restrict__ w4)
{
    int i = blockIdx.x * 256 + threadIdx.x;
    if (i >= WCTOT) return;
    if (i < WC0) {
        int n = i >> 9, k = i & 511;
        write2(g_wb1 + (size_t)n * 1024, 512, k, w1[n * 512 + k]);
    } else if (i < WC0 + WC1) {
        i -= WC0;
        int n = i >> 8, k = i & 255;
        write2(g_wb2 + (size_t)n * 512, 256, k, w2[n * 256 + k]);
    } else if (i < WC0 + WC1 + WC2) {
        i -= WC0 + WC1;
        int n = i / 448, k = i % 448;
        float v = (k < RDIM) ? w3[n * RDIM + k] : 0.0f;
        write2(g_wt0 + (size_t)n * 896, 448, k, v);
    } else {
        i -= WC0 + WC1 + WC2;
        int n = i >> 9, k = i & 511;
        write2(g_wt1 + (size_t)n * 1024, 512, k, w4[n * 512 + k]);
    }
}

// ---------------- bottom layer0: 13 -> 512, pair out -----------------------
#define B0_ROWS 32
__global__ void __launch_bounds__(256) bot0_kernel(
    const float* __restrict__ x,
    const float* __restrict__ w, const float* __restrict__ b)
{
    __shared__ float ws[512 * 13];
    __shared__ float bs[512];
    __shared__ float xs[B0_ROWS * 13];
    const int tid  = threadIdx.x;
    const int row0 = blockIdx.x * B0_ROWS;

    for (int i = tid; i < 512 * 13; i += 256) ws[i] = w[i];
    for (int i = tid; i < 512; i += 256)      bs[i] = b[i];
    for (int i = tid; i < B0_ROWS * 13; i += 256) xs[i] = x[row0 * 13 + i];
    __syncthreads();

    // paired outputs -> 4B packed stores instead of scattered 2B
    for (int o = tid; o < B0_ROWS * 256; o += 256) {
        int r = o >> 8, jp = (o & 255) * 2;
        const float* xr = xs + r * 13;
        const float* w0p = ws + jp * 13;
        const float* w1p = ws + (jp + 1) * 13;
        float a0 = bs[jp], a1 = bs[jp + 1];
#pragma unroll
        for (int k = 0; k < 13; k++) {
            float xv = xr[k];
            a0 += xv * w0p[k];
            a1 += xv * w1p[k];
        }
        store_pair2(g_h0 + (size_t)(row0 + r) * 1024 + jp, 512,
                    fmaxf(a0, 0.0f), fmaxf(a1, 0.0f));
    }
}

// ---------------- mma.sync bf16 GEMM, 3-stage cp.async ---------------------
// A2/W2: [hi|lo] pairs, stride 2*Kp; logical [hi|lo|hi]x[hi|hi|lo] via chunk
// remap. BM in {128,64}, BN=64, BK=64. 256 threads: 4(M)x2(N) warps.
// mode 0: fp32 out Cf[ldc]; mode 1: [hi|lo] pair out C2 (Kp=KpOut).
#define NSTAGE 3
template<int BM>
__global__ void __launch_bounds__(256, 3) gemm_mma(
    const __nv_bfloat16* __restrict__ A2,
    const __nv_bfloat16* __restrict__ W2,
    const float* __restrict__ bias, int Kp,
    float* __restrict__ Cf, int ldc,
    __nv_bfloat16* __restrict__ C2, int KpOut, int mode)
{
    constexpr int MT     = BM / 64;          // m16 frags per warp
    constexpr int NBA    = BM / 32;          // A cp.async per thread
    constexpr int ABYTES = BM * 128;
    constexpr int STAGEB = ABYTES + 64 * 128;

    extern __shared__ char dynsm[];
    const int tid  = threadIdx.x;
    const int wid  = tid >> 5;
    const int lane = tid & 31;
    const int warp_m = wid & 3;
    const int warp_n = wid >> 2;
    const size_t row0 = (size_t)blockIdx.x * BM;
    const size_t col0 = (size_t)blockIdx.y * 64;

    uint32_t dbase = smem_u32(dynsm);
    uint32_t abase = (dbase + 1023) & ~1023u;

    const int lrow = tid >> 3;
    const int lcol = tid & 7;
    const int K2 = 2 * Kp;
    const int nz  = Kp / 64;
    const int nch = 3 * nz;
    const __nv_bfloat16* Abase = A2 + (row0 + lrow) * (size_t)K2 + lcol * 8;
    const __nv_bfloat16* Wbase = W2 + (col0 + lrow) * (size_t)K2 + lcol * 8;
    const uint32_t adst = sw128(lrow * 128 + lcol * 16);   // row-q adds 32*128

    // issue chunk t's loads into stage s
    auto issue = [&](int t, int s) {
        const int at = (t < 2 * nz) ? t : t - 2 * nz;      // A: [hi|lo|hi]
        const int wt = (t < nz)     ? t : t - nz;          // W: [hi|hi|lo]
        const uint32_t sb = abase + s * STAGEB;
        const __nv_bfloat16* Ab = Abase + at * 64;
        const __nv_bfloat16* Wb = Wbase + wt * 64;
#pragma unroll
        for (int q = 0; q < NBA; q++)
            CP_ASYNC16(sb + adst + q * 32 * 128, Ab + (size_t)q * 32 * K2);
#pragma unroll
        for (int q = 0; q < 2; q++)
            CP_ASYNC16(sb + ABYTES + adst + q * 32 * 128, Wb + (size_t)q * 32 * K2);
    };

    // ldmatrix lane offsets (relative to stage base)
    int abyte[MT], bbyte[2];
#pragma unroll
    for (int tm = 0; tm < MT; tm++)
        abyte[tm] = (warp_m * MT * 16 + tm * 16 + (lane & 15)) * 128 + (lane >> 4) * 16;
#pragma unroll
    for (int g = 0; g < 2; g++)
        bbyte[g] = (warp_n * 32 + g * 16 + (lane & 15)) * 128 + (lane >> 4) * 16;

    // accumulators (+bias)
    float c[MT][4][4];
    {
        const int cb = (int)col0 + warp_n * 32 + 2 * (lane & 3);
#pragma unroll
        for (int tn = 0; tn < 4; tn++) {
            float b0v = bias[cb + tn * 8];
            float b1v = bias[cb + tn * 8 + 1];
#pragma unroll
            for (int tm = 0; tm < MT; tm++) {
                c[tm][tn][0] = b0v; c[tm][tn][1] = b1v;
                c[tm][tn][2] = b0v; c[tm][tn][3] = b1v;
            }
        }
    }

    // prologue: stages 0,1 in flight
    issue(0, 0); CP_COMMIT();
    issue(1, 1); CP_COMMIT();

    for (int t = 0; t < nch; t++) {
        __syncthreads();                       // all warps done with stage (t+2)%3
        if (t + 2 < nch) { issue(t + 2, (t + 2) % NSTAGE); CP_COMMIT(); }
        const int rem = nch - 1 - t;
        if (rem >= 2)      CP_WAIT(2);
        else if (rem == 1) CP_WAIT(1);
        else               CP_WAIT(0);
        __syncthreads();                       // stage t visible to all warps

        const uint32_t sbase = abase + (t % NSTAGE) * STAGEB;
        const uint32_t bbase = sbase + ABYTES;
#pragma unroll
        for (int s = 0; s < 4; s++) {
            uint32_t af[MT][4];
#pragma unroll
            for (int tm = 0; tm < MT; tm++)
                LDSM_X4(af[tm][0], af[tm][1], af[tm][2], af[tm][3],
                        sbase + sw128(abyte[tm] + s * 32));
            // serialize B groups: lower register pressure
#pragma unroll
            for (int g = 0; g < 2; g++) {
                uint32_t b0, b1, b2, b3;
                LDSM_X4(b0, b1, b2, b3, bbase + sw128(bbyte[g] + s * 32));
#pragma unroll
                for (int tm = 0; tm < MT; tm++) {
                    MMA16816(c[tm][g * 2 + 0],
                             af[tm][0], af[tm][1], af[tm][2], af[tm][3], b0, b2);
                    MMA16816(c[tm][g * 2 + 1],
                             af[tm][0], af[tm][1], af[tm][2], af[tm][3], b1, b3);
                }
            }
        }
    }

    // epilogue: fragments straight to global
#pragma unroll
    for (int tm = 0; tm < MT; tm++) {
        const size_t r = row0 + warp_m * MT * 16 + tm * 16 + (lane >> 2);
#pragma unroll
        for (int tn = 0; tn < 4; tn++) {
            const size_t cc = col0 + warp_n * 32 + tn * 8 + 2 * (lane & 3);
            float v0 = fmaxf(c[tm][tn][0], 0.0f);
            float v1 = fmaxf(c[tm][tn][1], 0.0f);
            float v2 = fmaxf(c[tm][tn][2], 0.0f);
            float v3 = fmaxf(c[tm][tn][3], 0.0f);
            if (mode == 0) {
                *(float2*)(Cf + r * ldc + cc)       = make_float2(v0, v1);
                *(float2*)(Cf + (r + 8) * ldc + cc) = make_float2(v2, v3);
            } else {
                store_pair2(C2 + r * (size_t)(2 * KpOut) + cc,       KpOut, v0, v1);
                store_pair2(C2 + (r + 8) * (size_t)(2 * KpOut) + cc, KpOut, v2, v3);
            }
        }
    }
}

// ---------------- embedding gather + interaction -> R pair -----------------
// R row staged in smem as bf16 [hi(448)|lo(448)], drained with uint4 stores.
__global__ void __launch_bounds__(256) embed_kernel(
    const void*  __restrict__ lsi_raw,
    const float* __restrict__ emb)
{
    __shared__ __align__(16) float F[NF * FSTR];
    __shared__ __align__(16) __nv_bfloat16 Rst[2 * RKP];
    __shared__ int sidx[NT * LOOKUPS];

    const int b    = blockIdx.x;
    const int tid  = threadIdx.x;
    const int is64 = g_idx64;

    if (tid < NT * LOOKUPS) {
        int t = tid >> 2, l = tid & 3;
        long long off = (long long)t * (BATCH * LOOKUPS) + (long long)b * LOOKUPS + l;
        int idx = is64 ? (int)((const long long*)lsi_raw)[off]
                       : ((const int*)lsi_raw)[off];
        sidx[tid] = idx;
    }
    if (tid < EDIM)
        F[tid] = g_xbot[(size_t)b * EDIM + tid];
    // zero the K-padding columns once
    if (tid >= 64 && tid < 64 + (RKP - RDIM)) {
        int j = RDIM + (tid - 64);
        Rst[j] = __float2bfloat16(0.0f);
        Rst[RKP + j] = __float2bfloat16(0.0f);
    }
    __syncthreads();

    for (int q = tid; q < NT * 16; q += 256) {
        int t = q >> 4, v = q & 15;
        const float4* base = (const float4*)(emb + (size_t)t * TROWS * EDIM) + v;
        float4 acc = make_float4(0.f, 0.f, 0.f, 0.f);
#pragma unroll
        for (int l = 0; l < LOOKUPS; l++) {
            float4 e = base[(size_t)sidx[t * 4 + l] * 16];
            acc.x += e.x; acc.y += e.y; acc.z += e.z; acc.w += e.w;
        }
        acc.x *= 0.25f; acc.y *= 0.25f; acc.z *= 0.25f; acc.w *= 0.25f;
        *(float4*)(F + (t + 1) * FSTR + v * 4) = acc;
    }
    __syncthreads();

    if (tid < EDIM) split2s(Rst, tid, F[tid]);

    for (int p = tid; p < NPAIR; p += 256) {
        int i = (int)((1.0f + sqrtf(1.0f + 8.0f * (float)p)) * 0.5f);
        while (i * (i - 1) / 2 > p) i--;
        while ((i + 1) * i / 2 <= p) i++;
        int j = p - i * (i - 1) / 2;
        const float* Fi = F + i * FSTR;
        const float* Fj = F + j * FSTR;
        float acc = 0.0f;
#pragma unroll 16
        for (int k = 0; k < EDIM; k++) acc += Fi[k] * Fj[k];
        split2s(Rst, 64 + p, acc);
    }
    __syncthreads();

    // coalesced drain: 896 bf16 = 1792B = 112 uint4
    if (tid < 112) {
        const uint4* src = (const uint4*)Rst;
        uint4* dst = (uint4*)(g_Rp + (size_t)b * 896);
        dst[tid] = src[tid];
    }
}

// ---------------- top layer2: 256 -> 1 (warp per row) ----------------------
__global__ void __launch_bounds__(256) top2_kernel(
    const float* __restrict__ A,
    const float* __restrict__ w, const float* __restrict__ b,
    float* __restrict__ out)
{
    const int warp = threadIdx.x >> 5, lane = threadIdx.x & 31;
    const int row  = blockIdx.x * 8 + warp;
    const float* a = A + (size_t)row * 256;
    float4 a0 = *(const float4*)(a + lane * 4);
    float4 a1 = *(const float4*)(a + 128 + lane * 4);
    float4 w0 = *(const float4*)(w + lane * 4);
    float4 w1 = *(const float4*)(w + 128 + lane * 4);
    float acc = a0.x * w0.x + a0.y * w0.y + a0.z * w0.z + a0.w * w0.w
              + a1.x * w1.x + a1.y * w1.y + a1.z * w1.z + a1.w * w1.w;
#pragma unroll
    for (int o = 16; o; o >>= 1) acc += __shfl_down_sync(0xffffffffu, acc, o);
    if (lane == 0) out[row] = acc + b[0];
}

// ---------------- launch ----------------
extern "C" void kernel_launch(void* const* d_in, const int* in_sizes, int n_in,
                              void* d_out, int out_size)
{
    const float* dense_x = (const float*)d_in[0];
    const void*  lsi     = d_in[2];
    const float* emb     = (const float*)d_in[3];
    const float* bw0 = (const float*)d_in[4];
    const float* bb0 = (const float*)d_in[5];
    const float* bw1 = (const float*)d_in[6];
    const float* bb1 = (const float*)d_in[7];
    const float* bw2 = (const float*)d_in[8];
    const float* bb2 = (const float*)d_in[9];
    const float* tw0 = (const float*)d_in[10];
    const float* tb0 = (const float*)d_in[11];
    const float* tw1 = (const float*)d_in[12];
    const float* tb1 = (const float*)d_in[13];
    const float* tw2 = (const float*)d_in[14];
    const float* tb2 = (const float*)d_in[15];
    float* out = (float*)d_out;

    __nv_bfloat16 *h0, *a1, *Rp, *t0, *wb1, *wb2, *wt0, *wt1;
    float *xbot, *t1;
    cudaGetSymbolAddress((void**)&h0,  g_h0);
    cudaGetSymbolAddress((void**)&a1,  g_a1);
    cudaGetSymbolAddress((void**)&Rp,  g_Rp);
    cudaGetSymbolAddress((void**)&t0,  g_t0);
    cudaGetSymbolAddress((void**)&wb1, g_wb1);
    cudaGetSymbolAddress((void**)&wb2, g_wb2);
    cudaGetSymbolAddress((void**)&wt0, g_wt0);
    cudaGetSymbolAddress((void**)&wt1, g_wt1);
    cudaGetSymbolAddress((void**)&xbot, g_xbot);
    cudaGetSymbolAddress((void**)&t1,   g_t1);

    const int dyn128 = 1024 + NSTAGE * (128 * 128 + 64 * 128);  // 74752
    const int dyn64  = 1024 + NSTAGE * (64 * 128 + 64 * 128);   // 50176
    cudaFuncSetAttribute(gemm_mma<128>, cudaFuncAttributeMaxDynamicSharedMemorySize, dyn128);
    cudaFuncSetAttribute(gemm_mma<64>,  cudaFuncAttributeMaxDynamicSharedMemorySize, dyn64);

    detect_kernel<<<1, 32>>>((const int*)lsi);
    wconv_all<<<(WCTOT + 255) / 256, 256>>>(bw1, bw2, tw0, tw1);

    // bottom MLP
    bot0_kernel<<<BATCH / B0_ROWS, 256>>>(dense_x, bw0, bb0);
    gemm_mma<128><<<dim3(BATCH / 128, 4), 256, dyn128>>>(h0, wb1, bb1, 512,
                                                         nullptr, 0, a1, 256, 1);
    gemm_mma<64><<<dim3(BATCH / 64, 1), 256, dyn64>>>(a1, wb2, bb2, 256,
                                                      xbot, 64, nullptr, 0, 0);
    // embeddings + interaction -> R pair
    embed_kernel<<<BATCH, 256>>>(lsi, emb);

    // top MLP
    gemm_mma<128><<<dim3(BATCH / 128, 8), 256, dyn128>>>(Rp, wt0, tb0, 448,
                                                         nullptr, 0, t0, 512, 1);
    gemm_mma<128><<<dim3(BATCH / 128, 4), 256, dyn128>>>(t0, wt1, tb1, 512,
                                                         t1, 256, nullptr, 0, 0);
    top2_kernel<<<BATCH / 8, 256>>>(t1, tw2, tb2, out);
}

// round 17
// speedup vs baseline: 1.1425x; 1.0435x over previous
#include <cuda_runtime.h>
#include <cuda_bf16.h>
#include <math.h>
#include <stdint.h>

// ---------------- problem constants ----------------
#define NT      26
#define TROWS   100001
#define EDIM    64
#define BATCH   8192
#define LOOKUPS 4
#define NF      27
#define NPAIR   351
#define RDIM    415
#define RKP     448
#define FSTR    68

// ---------------- scratch (allocation-free device globals) ----------------
// bf16 [hi|lo] pair buffers, row stride 2*Kp.
__device__ __align__(16) __nv_bfloat16 g_h0[(size_t)BATCH * 1024];  // Kp=512
__device__ __align__(16) __nv_bfloat16 g_a1[(size_t)BATCH * 512];   // Kp=256
__device__ __align__(16) __nv_bfloat16 g_Rp[(size_t)BATCH * 896];   // Kp=448
__device__ __align__(16) __nv_bfloat16 g_t0[(size_t)BATCH * 1024];  // Kp=512
__device__ __align__(16) float g_xbot[(size_t)BATCH * EDIM];
__device__ __align__(16) float g_t1[(size_t)BATCH * 256];
// weight [hi|lo] pairs
__device__ __align__(16) __nv_bfloat16 g_wb1[256 * 1024];
__device__ __align__(16) __nv_bfloat16 g_wb2[64  * 512];
__device__ __align__(16) __nv_bfloat16 g_wt0[512 * 896];
__device__ __align__(16) __nv_bfloat16 g_wt1[256 * 1024];
__device__ int g_idx64;

// ---------------- helpers ----------------
__device__ __forceinline__ uint32_t smem_u32(const void* p) {
    uint32_t a;
    asm("{ .reg .u64 t; cvta.to.shared.u64 t, %1; cvt.u32.u64 %0, t; }" : "=r"(a) : "l"(p));
    return a;
}
__device__ __forceinline__ uint32_t sw128(uint32_t o) { return o ^ ((o >> 3) & 0x70); }

#define CP_ASYNC16(dst, src) \
    asm volatile("cp.async.cg.shared.global [%0], [%1], 16;" :: "r"(dst), "l"(src))
#define CP_COMMIT() asm volatile("cp.async.commit_group;" ::: "memory")
#define CP_WAIT(n)  asm volatile("cp.async.wait_group %0;" :: "n"(n) : "memory")

#define LDSM_X4(r0, r1, r2, r3, a) \
    asm volatile("ldmatrix.sync.aligned.m8n8.x4.shared.b16 {%0,%1,%2,%3}, [%4];" \
                 : "=r"(r0), "=r"(r1), "=r"(r2), "=r"(r3) : "r"(a))

#define MMA16816(c, a0, a1, a2, a3, b0, b1) \
    asm volatile("mma.sync.aligned.m16n8k16.row.col.f32.bf16.bf16.f32 " \
                 "{%0,%1,%2,%3},{%4,%5,%6,%7},{%8,%9},{%0,%1,%2,%3};" \
                 : "+f"((c)[0]), "+f"((c)[1]), "+f"((c)[2]), "+f"((c)[3]) \
                 : "r"(a0), "r"(a1), "r"(a2), "r"(a3), "r"(b0), "r"(b1))

__device__ __forceinline__ void write2(__nv_bfloat16* row, int Kp, int j, float v) {
    __nv_bfloat16 hi = __float2bfloat16(v);
    __nv_bfloat16 lo = __float2bfloat16(v - __bfloat162float(hi));
    row[j] = hi; row[Kp + j] = lo;
}
__device__ __forceinline__ void store_pair2(__nv_bfloat16* base, int Kp,
                                            float v0, float v1) {
    __nv_bfloat16 h0 = __float2bfloat16(v0);
    __nv_bfloat16 h1 = __float2bfloat16(v1);
    __nv_bfloat16 l0 = __float2bfloat16(v0 - __bfloat162float(h0));
    __nv_bfloat16 l1 = __float2bfloat16(v1 - __bfloat162float(h1));
    *(__nv_bfloat162*)(base)      = __nv_bfloat162(h0, h1);
    *(__nv_bfloat162*)(base + Kp) = __nv_bfloat162(l0, l1);
}
// split into smem-staged hi/lo (bf16) halves
__device__ __forceinline__ void split2s(__nv_bfloat16* sm, int j, float v) {
    __nv_bfloat16 hi = __float2bfloat16(v);
    __nv_bfloat16 lo = __float2bfloat16(v - __bfloat162float(hi));
    sm[j] = hi; sm[RKP + j] = lo;
}

// ---------------- index dtype probe ----------------
__global__ void detect_kernel(const int* __restrict__ lsi_raw) {
    if (threadIdx.x == 0 && blockIdx.x == 0) {
        int ok = 1;
        for (int p = 0; p < 32; p++) {
            int lo = lsi_raw[2 * p], hi = lsi_raw[2 * p + 1];
            if (hi != 0 || (unsigned)lo > 100000u) { ok = 0; break; }
        }
        g_idx64 = ok;
    }
}

// ---------------- merged weight convert -----------------------------------
#define WC0 (256 * 512)
#define WC1 (64 * 256)
#define WC2 (512 * 448)
#define WC3 (256 * 512)
#define WCTOT (WC0 + WC1 + WC2 + WC3)
__global__ void wconv_all(const float* __restrict__ w1, const float* __restrict__ w2,
                          const float* __restrict__ w3, const float* __restrict__ w4)
{
    int i = blockIdx.x * 256 + threadIdx.x;
    if (i >= WCTOT) return;
    if (i < WC0) {
        int n = i >> 9, k = i & 511;
        write2(g_wb1 + (size_t)n * 1024, 512, k, w1[n * 512 + k]);
    } else if (i < WC0 + WC1) {
        i -= WC0;
        int n = i >> 8, k = i & 255;
        write2(g_wb2 + (size_t)n * 512, 256, k, w2[n * 256 + k]);
    } else if (i < WC0 + WC1 + WC2) {
        i -= WC0 + WC1;
        int n = i / 448, k = i % 448;
        float v = (k < RDIM) ? w3[n * RDIM + k] : 0.0f;
        write2(g_wt0 + (size_t)n * 896, 448, k, v);
    } else {
        i -= WC0 + WC1 + WC2;
        int n = i >> 9, k = i & 511;
        write2(g_wt1 + (size_t)n * 1024, 512, k, w4[n * 512 + k]);
    }
}

// ---------------- bottom layer0: 13 -> 512, pair out -----------------------
#define B0_ROWS 32
__global__ void __launch_bounds__(256) bot0_kernel(
    const float* __restrict__ x,
    const float* __restrict__ w, const float* __restrict__ b)
{
    __shared__ float ws[512 * 13];
    __shared__ float bs[512];
    __shared__ float xs[B0_ROWS * 13];
    const int tid  = threadIdx.x;
    const int row0 = blockIdx.x * B0_ROWS;

    for (int i = tid; i < 512 * 13; i += 256) ws[i] = w[i];
    for (int i = tid; i < 512; i += 256)      bs[i] = b[i];
    for (int i = tid; i < B0_ROWS * 13; i += 256) xs[i] = x[row0 * 13 + i];
    __syncthreads();

    for (int o = tid; o < B0_ROWS * 256; o += 256) {
        int r = o >> 8, jp = (o & 255) * 2;
        const float* xr = xs + r * 13;
        const float* w0p = ws + jp * 13;
        const float* w1p = ws + (jp + 1) * 13;
        float a0 = bs[jp], a1 = bs[jp + 1];
#pragma unroll
        for (int k = 0; k < 13; k++) {
            float xv = xr[k];
            a0 += xv * w0p[k];
            a1 += xv * w1p[k];
        }
        store_pair2(g_h0 + (size_t)(row0 + r) * 1024 + jp, 512,
                    fmaxf(a0, 0.0f), fmaxf(a1, 0.0f));
    }
}

// ---------------- mma.sync bf16 GEMM, tile-reuse mainloop ------------------
// A2/W2: [hi|lo] pairs, stride 2*Kp. Per 64-wide k-block z we stage 4 tiles
// {A-hi, A-lo, W-hi, W-lo} ONCE and run the 3 logical passes
// (hi*hi + lo*hi + hi*lo) from them, reusing A-hi and W-hi fragments in
// registers. 2-stage ping-pong cp.async. BM in {128,64}, BN=64, BK=64.
// mode 0: fp32 out Cf[ldc]; mode 1: [hi|lo] pair out C2 (Kp=KpOut).
template<int BM>
__global__ void __launch_bounds__(256, (BM == 128 ? 2 : 3)) gemm_mma(
    const __nv_bfloat16* __restrict__ A2,
    const __nv_bfloat16* __restrict__ W2,
    const float* __restrict__ bias, int Kp,
    float* __restrict__ Cf, int ldc,
    __nv_bfloat16* __restrict__ C2, int KpOut, int mode)
{
    constexpr int MT     = BM / 64;          // m16 frags per warp
    constexpr int NBA    = BM / 32;          // cp.async per thread per A tile
    constexpr int AB     = BM * 128;         // one A tile bytes
    constexpr int WB     = 64 * 128;         // one W tile bytes
    constexpr int STAGEB = 2 * AB + 2 * WB;  // {Ahi, Alo, Whi, Wlo}

    extern __shared__ char dynsm[];
    const int tid  = threadIdx.x;
    const int lane = tid & 31;
    const int wid  = tid >> 5;
    const int warp_m = wid & 3;
    const int warp_n = wid >> 2;
    const size_t row0 = (size_t)blockIdx.x * BM;
    const size_t col0 = (size_t)blockIdx.y * 64;

    uint32_t dbase = smem_u32(dynsm);
    uint32_t abase = (dbase + 1023) & ~1023u;

    const int lrow = tid >> 3;
    const int lcol = tid & 7;
    const int K2 = 2 * Kp;
    const int nz = Kp / 64;
    const __nv_bfloat16* Abase = A2 + (row0 + lrow) * (size_t)K2 + lcol * 8;
    const __nv_bfloat16* Wbase = W2 + (col0 + lrow) * (size_t)K2 + lcol * 8;
    const uint32_t adst = sw128(lrow * 128 + lcol * 16);   // row-q adds 32*128

    // stage the 4 tiles of k-block z into stage s
    auto issue = [&](int z, int s) {
        const uint32_t sb = abase + s * STAGEB;
        const __nv_bfloat16* Ahi = Abase + z * 64;
        const __nv_bfloat16* Alo = Abase + Kp + z * 64;
        const __nv_bfloat16* Whi = Wbase + z * 64;
        const __nv_bfloat16* Wlo = Wbase + Kp + z * 64;
#pragma unroll
        for (int q = 0; q < NBA; q++)
            CP_ASYNC16(sb + adst + q * 32 * 128, Ahi + (size_t)q * 32 * K2);
#pragma unroll
        for (int q = 0; q < NBA; q++)
            CP_ASYNC16(sb + AB + adst + q * 32 * 128, Alo + (size_t)q * 32 * K2);
#pragma unroll
        for (int q = 0; q < 2; q++)
            CP_ASYNC16(sb + 2 * AB + adst + q * 32 * 128, Whi + (size_t)q * 32 * K2);
#pragma unroll
        for (int q = 0; q < 2; q++)
            CP_ASYNC16(sb + 2 * AB + WB + adst + q * 32 * 128, Wlo + (size_t)q * 32 * K2);
    };

    // ldmatrix lane offsets (relative to tile base)
    int abyte[MT], bbyte[2];
#pragma unroll
    for (int tm = 0; tm < MT; tm++)
        abyte[tm] = (warp_m * MT * 16 + tm * 16 + (lane & 15)) * 128 + (lane >> 4) * 16;
#pragma unroll
    for (int g = 0; g < 2; g++)
        bbyte[g] = (warp_n * 32 + g * 16 + (lane & 15)) * 128 + (lane >> 4) * 16;

    // accumulators (+bias)
    float c[MT][4][4];
    {
        const int cb = (int)col0 + warp_n * 32 + 2 * (lane & 3);
#pragma unroll
        for (int tn = 0; tn < 4; tn++) {
            float b0v = bias[cb + tn * 8];
            float b1v = bias[cb + tn * 8 + 1];
#pragma unroll
            for (int tm = 0; tm < MT; tm++) {
                c[tm][tn][0] = b0v; c[tm][tn][1] = b1v;
                c[tm][tn][2] = b0v; c[tm][tn][3] = b1v;
            }
        }
    }

    // prologue: stages 0,1 in flight
    issue(0, 0); CP_COMMIT();
    if (nz > 1) { issue(1, 1); CP_COMMIT(); }

    for (int z = 0; z < nz; z++) {
        if (z + 1 < nz) CP_WAIT(1);
        else            CP_WAIT(0);
        __syncthreads();                       // stage z visible to all warps

        const uint32_t sbase = abase + (z & 1) * STAGEB;
#pragma unroll
        for (int s = 0; s < 4; s++) {
            uint32_t ah[MT][4], al[MT][4];
#pragma unroll
            for (int tm = 0; tm < MT; tm++)
                LDSM_X4(ah[tm][0], ah[tm][1], ah[tm][2], ah[tm][3],
                        sbase + sw128(abyte[tm] + s * 32));
#pragma unroll
            for (int tm = 0; tm < MT; tm++)
                LDSM_X4(al[tm][0], al[tm][1], al[tm][2], al[tm][3],
                        sbase + AB + sw128(abyte[tm] + s * 32));
#pragma unroll
            for (int g = 0; g < 2; g++) {
                uint32_t b0, b1, b2, b3;
                // W-hi: passes hi*hi and lo*hi share these fragments
                LDSM_X4(b0, b1, b2, b3, sbase + 2 * AB + sw128(bbyte[g] + s * 32));
#pragma unroll
                for (int tm = 0; tm < MT; tm++) {
                    MMA16816(c[tm][g * 2 + 0], ah[tm][0], ah[tm][1], ah[tm][2], ah[tm][3], b0, b2);
                    MMA16816(c[tm][g * 2 + 1], ah[tm][0], ah[tm][1], ah[tm][2], ah[tm][3], b1, b3);
                    MMA16816(c[tm][g * 2 + 0], al[tm][0], al[tm][1], al[tm][2], al[tm][3], b0, b2);
                    MMA16816(c[tm][g * 2 + 1], al[tm][0], al[tm][1], al[tm][2], al[tm][3], b1, b3);
                }
                // W-lo: pass hi*lo reuses the A-hi fragments
                LDSM_X4(b0, b1, b2, b3, sbase + 2 * AB + WB + sw128(bbyte[g] + s * 32));
#pragma unroll
                for (int tm = 0; tm < MT; tm++) {
                    MMA16816(c[tm][g * 2 + 0], ah[tm][0], ah[tm][1], ah[tm][2], ah[tm][3], b0, b2);
                    MMA16816(c[tm][g * 2 + 1], ah[tm][0], ah[tm][1], ah[tm][2], ah[tm][3], b1, b3);
                }
            }
        }
        __syncthreads();                       // all warps done reading stage
        if (z + 2 < nz) { issue(z + 2, z & 1); CP_COMMIT(); }
    }

    // epilogue: fragments straight to global
#pragma unroll
    for (int tm = 0; tm < MT; tm++) {
        const size_t r = row0 + warp_m * MT * 16 + tm * 16 + (lane >> 2);
#pragma unroll
        for (int tn = 0; tn < 4; tn++) {
            const size_t cc = col0 + warp_n * 32 + tn * 8 + 2 * (lane & 3);
            float v0 = fmaxf(c[tm][tn][0], 0.0f);
            float v1 = fmaxf(c[tm][tn][1], 0.0f);
            float v2 = fmaxf(c[tm][tn][2], 0.0f);
            float v3 = fmaxf(c[tm][tn][3], 0.0f);
            if (mode == 0) {
                *(float2*)(Cf + r * ldc + cc)       = make_float2(v0, v1);
                *(float2*)(Cf + (r + 8) * ldc + cc) = make_float2(v2, v3);
            } else {
                store_pair2(C2 + r * (size_t)(2 * KpOut) + cc,       KpOut, v0, v1);
                store_pair2(C2 + (r + 8) * (size_t)(2 * KpOut) + cc, KpOut, v2, v3);
            }
        }
    }
}

// ---------------- embedding gather + interaction -> R pair -----------------
// R row staged in smem as bf16 [hi(448)|lo(448)], drained with uint4 stores.
__global__ void __launch_bounds__(256) embed_kernel(
    const void*  __restrict__ lsi_raw,
    const float* __restrict__ emb)
{
    __shared__ __align__(16) float F[NF * FSTR];
    __shared__ __align__(16) __nv_bfloat16 Rst[2 * RKP];
    __shared__ int sidx[NT * LOOKUPS];

    const int b    = blockIdx.x;
    const int tid  = threadIdx.x;
    const int is64 = g_idx64;

    if (tid < NT * LOOKUPS) {
        int t = tid >> 2, l = tid & 3;
        long long off = (long long)t * (BATCH * LOOKUPS) + (long long)b * LOOKUPS + l;
        int idx = is64 ? (int)((const long long*)lsi_raw)[off]
                       : ((const int*)lsi_raw)[off];
        sidx[tid] = idx;
    }
    if (tid < EDIM)
        F[tid] = g_xbot[(size_t)b * EDIM + tid];
    if (tid >= 64 && tid < 64 + (RKP - RDIM)) {
        int j = RDIM + (tid - 64);
        Rst[j] = __float2bfloat16(0.0f);
        Rst[RKP + j] = __float2bfloat16(0.0f);
    }
    __syncthreads();

    for (int q = tid; q < NT * 16; q += 256) {
        int t = q >> 4, v = q & 15;
        const float4* base = (const float4*)(emb + (size_t)t * TROWS * EDIM) + v;
        float4 acc = make_float4(0.f, 0.f, 0.f, 0.f);
#pragma unroll
        for (int l = 0; l < LOOKUPS; l++) {
            float4 e = base[(size_t)sidx[t * 4 + l] * 16];
            acc.x += e.x; acc.y += e.y; acc.z += e.z; acc.w += e.w;
        }
        acc.x *= 0.25f; acc.y *= 0.25f; acc.z *= 0.25f; acc.w *= 0.25f;
        *(float4*)(F + (t + 1) * FSTR + v * 4) = acc;
    }
    __syncthreads();

    if (tid < EDIM) split2s(Rst, tid, F[tid]);

    for (int p = tid; p < NPAIR; p += 256) {
        int i = (int)((1.0f + sqrtf(1.0f + 8.0f * (float)p)) * 0.5f);
        while (i * (i - 1) / 2 > p) i--;
        while ((i + 1) * i / 2 <= p) i++;
        int j = p - i * (i - 1) / 2;
        const float* Fi = F + i * FSTR;
        const float* Fj = F + j * FSTR;
        float acc = 0.0f;
#pragma unroll 16
        for (int k = 0; k < EDIM; k++) acc += Fi[k] * Fj[k];
        split2s(Rst, 64 + p, acc);
    }
    __syncthreads();

    if (tid < 112) {
        const uint4* src = (const uint4*)Rst;
        uint4* dst = (uint4*)(g_Rp + (size_t)b * 896);
        dst[tid] = src[tid];
    }
}

// ---------------- top layer2: 256 -> 1 (warp per row) ----------------------
__global__ void __launch_bounds__(256) top2_kernel(
    const float* __restrict__ A,
    const float* __restrict__ w, const float* __restrict__ b,
    float* __restrict__ out)
{
    const int warp = threadIdx.x >> 5, lane = threadIdx.x & 31;
    const int row  = blockIdx.x * 8 + warp;
    const float* a = A + (size_t)row * 256;
    float4 a0 = *(const float4*)(a + lane * 4);
    float4 a1 = *(const float4*)(a + 128 + lane * 4);
    float4 w0 = *(const float4*)(w + lane * 4);
    float4 w1 = *(const float4*)(w + 128 + lane * 4);
    float acc = a0.x * w0.x + a0.y * w0.y + a0.z * w0.z + a0.w * w0.w
              + a1.x * w1.x + a1.y * w1.y + a1.z * w1.z + a1.w * w1.w;
#pragma unroll
    for (int o = 16; o; o >>= 1) acc += __shfl_down_sync(0xffffffffu, acc, o);
    if (lane == 0) out[row] = acc + b[0];
}

// ---------------- launch ----------------
extern "C" void kernel_launch(void* const* d_in, const int* in_sizes, int n_in,
                              void* d_out, int out_size)
{
    const float* dense_x = (const float*)d_in[0];
    const void*  lsi     = d_in[2];
    const float* emb     = (const float*)d_in[3];
    const float* bw0 = (const float*)d_in[4];
    const float* bb0 = (const float*)d_in[5];
    const float* bw1 = (const float*)d_in[6];
    const float* bb1 = (const float*)d_in[7];
    const float* bw2 = (const float*)d_in[8];
    const float* bb2 = (const float*)d_in[9];
    const float* tw0 = (const float*)d_in[10];
    const float* tb0 = (const float*)d_in[11];
    const float* tw1 = (const float*)d_in[12];
    const float* tb1 = (const float*)d_in[13];
    const float* tw2 = (const float*)d_in[14];
    const float* tb2 = (const float*)d_in[15];
    float* out = (float*)d_out;

    __nv_bfloat16 *h0, *a1, *Rp, *t0, *wb1, *wb2, *wt0, *wt1;
    float *xbot, *t1;
    cudaGetSymbolAddress((void**)&h0,  g_h0);
    cudaGetSymbolAddress((void**)&a1,  g_a1);
    cudaGetSymbolAddress((void**)&Rp,  g_Rp);
    cudaGetSymbolAddress((void**)&t0,  g_t0);
    cudaGetSymbolAddress((void**)&wb1, g_wb1);
    cudaGetSymbolAddress((void**)&wb2, g_wb2);
    cudaGetSymbolAddress((void**)&wt0, g_wt0);
    cudaGetSymbolAddress((void**)&wt1, g_wt1);
    cudaGetSymbolAddress((void**)&xbot, g_xbot);
    cudaGetSymbolAddress((void**)&t1,   g_t1);

    // stage = 2*A + 2*W tiles, 2 stages + alignment pad
    const int dyn128 = 1024 + 2 * (2 * 128 * 128 + 2 * 64 * 128);  // 99328
    const int dyn64  = 1024 + 2 * (2 * 64 * 128 + 2 * 64 * 128);   // 66560
    cudaFuncSetAttribute(gemm_mma<128>, cudaFuncAttributeMaxDynamicSharedMemorySize, dyn128);
    cudaFuncSetAttribute(gemm_mma<64>,  cudaFuncAttributeMaxDynamicSharedMemorySize, dyn64);

    detect_kernel<<<1, 32>>>((const int*)lsi);
    wconv_all<<<(WCTOT + 255) / 256, 256>>>(bw1, bw2, tw0, tw1);

    // bottom MLP
    bot0_kernel<<<BATCH / B0_ROWS, 256>>>(dense_x, bw0, bb0);
    gemm_mma<128><<<dim3(BATCH / 128, 4), 256, dyn128>>>(h0, wb1, bb1, 512,
                                                         nullptr, 0, a1, 256, 1);
    gemm_mma<64><<<dim3(BATCH / 64, 1), 256, dyn64>>>(a1, wb2, bb2, 256,
                                                      xbot, 64, nullptr, 0, 0);
    // embeddings + interaction -> R pair
    embed_kernel<<<BATCH, 256>>>(lsi, emb);

    // top MLP
    gemm_mma<128><<<dim3(BATCH / 128, 8), 256, dyn128>>>(Rp, wt0, tb0, 448,
                                                         nullptr, 0, t0, 512, 1);
    gemm_mma<128><<<dim3(BATCH / 128, 4), 256, dyn128>>>(t0, wt1, tb1, 512,
                                                         t1, 256, nullptr, 0, 0);
    top2_kernel<<<BATCH / 8, 256>>>(t1, tw2, tb2, out);
}